// round 1
// baseline (speedup 1.0000x reference)
#include <cuda_runtime.h>

// Problem constants
#define E_   8
#define B_   16384
#define DS_  32
#define DA_  8
#define DIN_ 40
#define HID_ 128

// Tiling
#define TB_       64     // batch rows per CTA
#define NTHREADS_ 256
#define HSTR_     132    // padded stride for activation buffers (kills bank conflicts)

// SMEM layout (floats):
//  inp : TB*DIN          = 2560
//  w0  : DIN*HID         = 5120
//  w1  : HID*HID         = 16384
//  w2  : HID*DS          = 4096
//  b0  : HID             = 128
//  b1  : HID             = 128
//  b2  : DS              = 32
//  h0  : TB*HSTR         = 8448
//  h1  : TB*HSTR         = 8448
//  total = 45344 floats  = 181376 bytes
#define SMEM_FLOATS_ (TB_*DIN_ + DIN_*HID_ + HID_*HID_ + HID_*DS_ + HID_ + HID_ + DS_ + 2*TB_*HSTR_)

__global__ __launch_bounds__(NTHREADS_, 1)
void ensemble_mlp_kernel(const float* __restrict__ states,
                         const float* __restrict__ actions,
                         const float* __restrict__ W0, const float* __restrict__ b0,
                         const float* __restrict__ W1, const float* __restrict__ b1,
                         const float* __restrict__ W2, const float* __restrict__ b2,
                         float* __restrict__ out)
{
    extern __shared__ float sm[];
    float* s_inp = sm;                        // [TB][DIN]
    float* s_w0  = s_inp + TB_ * DIN_;        // [DIN][HID]
    float* s_w1  = s_w0  + DIN_ * HID_;       // [HID][HID]
    float* s_w2  = s_w1  + HID_ * HID_;       // [HID][DS]
    float* s_b0  = s_w2  + HID_ * DS_;        // [HID]
    float* s_b1  = s_b0  + HID_;              // [HID]
    float* s_b2  = s_b1  + HID_;              // [DS]
    float* s_h0  = s_b2  + DS_;               // [TB][HSTR]
    float* s_h1  = s_h0  + TB_ * HSTR_;       // [TB][HSTR]

    const int tid   = threadIdx.x;
    const int j     = blockIdx.y;             // ensemble member (weights)
    const int btile = blockIdx.x * TB_;       // batch tile start

    // ---- stage weights & biases for member j ----
    {
        const float* w0g = W0 + (size_t)j * DIN_ * HID_;
        const float* w1g = W1 + (size_t)j * HID_ * HID_;
        const float* w2g = W2 + (size_t)j * HID_ * DS_;
        for (int idx = tid; idx < DIN_ * HID_; idx += NTHREADS_) s_w0[idx] = w0g[idx];
        for (int idx = tid; idx < HID_ * HID_; idx += NTHREADS_) s_w1[idx] = w1g[idx];
        for (int idx = tid; idx < HID_ * DS_;  idx += NTHREADS_) s_w2[idx] = w2g[idx];
        if (tid < HID_) { s_b0[tid] = b0[j * HID_ + tid]; s_b1[tid] = b1[j * HID_ + tid]; }
        if (tid < DS_)  { s_b2[tid] = b2[j * DS_ + tid]; }
    }

    // thread -> output micro-tile mapping (16x16 thread grid)
    const int ty = tid >> 4;       // 0..15
    const int tx = tid & 15;       // 0..15
    const int r0 = ty * 4;         // 4 rows / thread
    const int c0 = tx * 8;         // 8 cols / thread (layers 0,1)
    const int c2 = tx * 2;         // 2 cols / thread (layer 2)

    float sum[4][2]   = {{0.f,0.f},{0.f,0.f},{0.f,0.f},{0.f,0.f}};
    float sumsq[4][2] = {{0.f,0.f},{0.f,0.f},{0.f,0.f},{0.f,0.f}};

    __syncthreads();  // weights visible

    for (int i = 0; i < E_; ++i) {
        // ---- load input tile: inp = concat(states[i], actions[i]) ----
        for (int idx = tid; idx < TB_ * DS_; idx += NTHREADS_) {
            int b = idx / DS_, d = idx - b * DS_;
            s_inp[b * DIN_ + d] = states[((size_t)i * B_ + btile + b) * DS_ + d];
        }
        for (int idx = tid; idx < TB_ * DA_; idx += NTHREADS_) {
            int b = idx / DA_, d = idx - b * DA_;
            s_inp[b * DIN_ + DS_ + d] = actions[((size_t)i * B_ + btile + b) * DA_ + d];
        }
        __syncthreads();

        // ---- layer 0: h0 = leaky(inp @ W0 + b0)   [TB x HID], K=40 ----
        {
            float acc[4][8];
            #pragma unroll
            for (int r = 0; r < 4; ++r)
                #pragma unroll
                for (int c = 0; c < 8; ++c) acc[r][c] = 0.f;

            #pragma unroll 8
            for (int k = 0; k < DIN_; ++k) {
                float a[4];
                #pragma unroll
                for (int r = 0; r < 4; ++r) a[r] = s_inp[(r0 + r) * DIN_ + k];
                float4 bv0 = *(const float4*)&s_w0[k * HID_ + c0];
                float4 bv1 = *(const float4*)&s_w0[k * HID_ + c0 + 4];
                float bw[8] = {bv0.x, bv0.y, bv0.z, bv0.w, bv1.x, bv1.y, bv1.z, bv1.w};
                #pragma unroll
                for (int r = 0; r < 4; ++r)
                    #pragma unroll
                    for (int c = 0; c < 8; ++c)
                        acc[r][c] = fmaf(a[r], bw[c], acc[r][c]);
            }
            #pragma unroll
            for (int r = 0; r < 4; ++r) {
                #pragma unroll
                for (int c = 0; c < 8; ++c) {
                    float v = acc[r][c] + s_b0[c0 + c];
                    acc[r][c] = v > 0.f ? v : 0.01f * v;
                }
                *(float4*)&s_h0[(r0 + r) * HSTR_ + c0]     = make_float4(acc[r][0], acc[r][1], acc[r][2], acc[r][3]);
                *(float4*)&s_h0[(r0 + r) * HSTR_ + c0 + 4] = make_float4(acc[r][4], acc[r][5], acc[r][6], acc[r][7]);
            }
        }
        __syncthreads();

        // ---- layer 1: h1 = leaky(h0 @ W1 + b1)   [TB x HID], K=128 ----
        {
            float acc[4][8];
            #pragma unroll
            for (int r = 0; r < 4; ++r)
                #pragma unroll
                for (int c = 0; c < 8; ++c) acc[r][c] = 0.f;

            #pragma unroll 8
            for (int k = 0; k < HID_; ++k) {
                float a[4];
                #pragma unroll
                for (int r = 0; r < 4; ++r) a[r] = s_h0[(r0 + r) * HSTR_ + k];
                float4 bv0 = *(const float4*)&s_w1[k * HID_ + c0];
                float4 bv1 = *(const float4*)&s_w1[k * HID_ + c0 + 4];
                float bw[8] = {bv0.x, bv0.y, bv0.z, bv0.w, bv1.x, bv1.y, bv1.z, bv1.w};
                #pragma unroll
                for (int r = 0; r < 4; ++r)
                    #pragma unroll
                    for (int c = 0; c < 8; ++c)
                        acc[r][c] = fmaf(a[r], bw[c], acc[r][c]);
            }
            #pragma unroll
            for (int r = 0; r < 4; ++r) {
                #pragma unroll
                for (int c = 0; c < 8; ++c) {
                    float v = acc[r][c] + s_b1[c0 + c];
                    acc[r][c] = v > 0.f ? v : 0.01f * v;
                }
                *(float4*)&s_h1[(r0 + r) * HSTR_ + c0]     = make_float4(acc[r][0], acc[r][1], acc[r][2], acc[r][3]);
                *(float4*)&s_h1[(r0 + r) * HSTR_ + c0 + 4] = make_float4(acc[r][4], acc[r][5], acc[r][6], acc[r][7]);
            }
        }
        __syncthreads();

        // ---- layer 2: pred = h1 @ W2 + b2   [TB x DS], K=128 ; accumulate stats ----
        {
            float acc[4][2];
            #pragma unroll
            for (int r = 0; r < 4; ++r) { acc[r][0] = 0.f; acc[r][1] = 0.f; }

            #pragma unroll 8
            for (int k = 0; k < HID_; ++k) {
                float a[4];
                #pragma unroll
                for (int r = 0; r < 4; ++r) a[r] = s_h1[(r0 + r) * HSTR_ + k];
                float w0v = s_w2[k * DS_ + c2];
                float w1v = s_w2[k * DS_ + c2 + 1];
                #pragma unroll
                for (int r = 0; r < 4; ++r) {
                    acc[r][0] = fmaf(a[r], w0v, acc[r][0]);
                    acc[r][1] = fmaf(a[r], w1v, acc[r][1]);
                }
            }
            #pragma unroll
            for (int r = 0; r < 4; ++r)
                #pragma unroll
                for (int c = 0; c < 2; ++c) {
                    float p = acc[r][c] + s_b2[c2 + c];
                    sum[r][c]   += p;
                    sumsq[r][c] = fmaf(p, p, sumsq[r][c]);
                }
        }
        __syncthreads();  // protect s_inp/s_h0/s_h1 before next i overwrites
    }

    // ---- epilogue: mean/var over i, add states[j], write both outputs ----
    const size_t var_off = (size_t)E_ * B_ * DS_;
    #pragma unroll
    for (int r = 0; r < 4; ++r) {
        const size_t b = (size_t)btile + r0 + r;
        #pragma unroll
        for (int c = 0; c < 2; ++c) {
            const int k = c2 + c;
            const size_t o = ((size_t)j * B_ + b) * DS_ + k;
            float mean = sum[r][c] * (1.0f / E_);
            float var  = (sumsq[r][c] - (float)E_ * mean * mean) * (1.0f / (E_ - 1));
            out[o]           = mean + states[o];   // next_state_mean
            out[var_off + o] = var;                // unbiased variance
        }
    }
}

extern "C" void kernel_launch(void* const* d_in, const int* in_sizes, int n_in,
                              void* d_out, int out_size)
{
    const float* states  = (const float*)d_in[0];
    const float* actions = (const float*)d_in[1];
    const float* W0      = (const float*)d_in[2];
    const float* b0      = (const float*)d_in[3];
    const float* W1      = (const float*)d_in[4];
    const float* b1      = (const float*)d_in[5];
    const float* W2      = (const float*)d_in[6];
    const float* b2      = (const float*)d_in[7];
    float* out = (float*)d_out;

    const int smem_bytes = SMEM_FLOATS_ * (int)sizeof(float);
    cudaFuncSetAttribute(ensemble_mlp_kernel,
                         cudaFuncAttributeMaxDynamicSharedMemorySize, smem_bytes);

    dim3 grid(B_ / TB_, E_);   // 256 x 8 = 2048 CTAs
    dim3 block(NTHREADS_);
    ensemble_mlp_kernel<<<grid, block, smem_bytes>>>(states, actions,
                                                     W0, b0, W1, b1, W2, b2, out);
}

// round 2
// speedup vs baseline: 1.1939x; 1.1939x over previous
#include <cuda_runtime.h>

// Problem constants
#define E_   8
#define B_   16384
#define DS_  32
#define DA_  8
#define DIN_ 40
#define HID_ 128

// Tiling
#define TB_   64      // batch rows per CTA
#define NTH_  256     // threads per CTA (16x16 grid: ty rows, tx cols)

// SMEM strides (floats). All row bases 16B-aligned.
#define ISTR_ 44      // inp  [TB][ISTR]   (DIN=40 cols used)
#define HSTR_ 132     // h0/h1[TB][HSTR]   (128 cols used; 528B rows, 16B-aligned)
#define W0K_  64      // w0t  [128 c][W0K k]  (k in 0..39, swizzled granules need <=15)
#define W1K_  128     // w1t  [128 c][128 k]
#define W2K_  128     // w2t  [ 32 c][128 k]

#define SMEM_FLOATS_ (TB_*ISTR_ + HID_*W0K_ + HID_*W1K_ + DS_*W2K_ + HID_ + HID_ + DS_ + 2*TB_*HSTR_)

// packed fp32x2 FMA (SASS FFMA2): d = a*b + c per 32-bit lane of the 64-bit reg
__device__ __forceinline__ unsigned long long ffma2(unsigned long long a,
                                                    unsigned long long b,
                                                    unsigned long long c) {
    unsigned long long d;
    asm("fma.rn.f32x2 %0, %1, %2, %3;" : "=l"(d) : "l"(a), "l"(b), "l"(c));
    return d;
}
__device__ __forceinline__ float hsum2(unsigned long long v) {
    float lo, hi;
    asm("mov.b64 {%0, %1}, %2;" : "=f"(lo), "=f"(hi) : "l"(v));
    return lo + hi;
}

// swizzled offset into a transposed weight tile: element (k, c), row stride kstr.
// granule = 16B (4 floats) along k; XOR key spreads the 16 tx-lanes over banks.
__device__ __forceinline__ int swz(int k, int c, int kstr) {
    int key = ((c >> 3) ^ c) & 7;
    return c * kstr + ((((k >> 2) ^ key)) << 2) + (k & 3);
}

__global__ __launch_bounds__(NTH_, 1)
void ensemble_mlp_kernel(const float* __restrict__ states,
                         const float* __restrict__ actions,
                         const float* __restrict__ W0, const float* __restrict__ b0,
                         const float* __restrict__ W1, const float* __restrict__ b1,
                         const float* __restrict__ W2, const float* __restrict__ b2,
                         float* __restrict__ out)
{
    extern __shared__ float sm[];
    float* s_inp = sm;                         // [TB][ISTR]
    float* s_w0t = s_inp + TB_ * ISTR_;        // [128][W0K]  (transposed, swizzled)
    float* s_w1t = s_w0t + HID_ * W0K_;        // [128][W1K]
    float* s_w2t = s_w1t + HID_ * W1K_;        // [ 32][W2K]
    float* s_b0  = s_w2t + DS_ * W2K_;         // [128]
    float* s_b1  = s_b0  + HID_;               // [128]
    float* s_b2  = s_b1  + HID_;               // [32]
    float* s_h0  = s_b2  + DS_;                // [TB][HSTR]
    float* s_h1  = s_h0  + TB_ * HSTR_;        // [TB][HSTR]

    const int tid   = threadIdx.x;
    const int j     = blockIdx.y;
    const int btile = blockIdx.x * TB_;

    // ---- stage weights transposed + swizzled ----
    {
        const float* w0g = W0 + (size_t)j * DIN_ * HID_;   // [40][128]
        const float* w1g = W1 + (size_t)j * HID_ * HID_;   // [128][128]
        const float* w2g = W2 + (size_t)j * HID_ * DS_;    // [128][32]
        for (int idx = tid; idx < DIN_ * HID_; idx += NTH_) {
            int k = idx >> 7, c = idx & 127;
            s_w0t[swz(k, c, W0K_)] = w0g[idx];
        }
        for (int idx = tid; idx < HID_ * HID_; idx += NTH_) {
            int k = idx >> 7, c = idx & 127;
            s_w1t[swz(k, c, W1K_)] = w1g[idx];
        }
        for (int idx = tid; idx < HID_ * DS_; idx += NTH_) {
            int k = idx >> 5, c = idx & 31;
            s_w2t[swz(k, c, W2K_)] = w2g[idx];
        }
        if (tid < HID_) { s_b0[tid] = b0[j * HID_ + tid]; s_b1[tid] = b1[j * HID_ + tid]; }
        if (tid < DS_)  { s_b2[tid] = b2[j * DS_ + tid]; }
    }

    const int ty = tid >> 4;       // 0..15
    const int tx = tid & 15;       // 0..15
    const int r0 = ty * 4;         // 4 rows / thread
    const int c0 = tx * 8;         // 8 cols / thread (layers 0,1)
    const int c2 = tx * 2;         // 2 cols / thread (layer 2)

    // per-column swizzle keys (constant over k)
    int key1[8];
    #pragma unroll
    for (int cc = 0; cc < 8; ++cc) key1[cc] = (tx ^ cc) & 7;          // c = 8*tx+cc
    int key2[2];
    #pragma unroll
    for (int cc = 0; cc < 2; ++cc) {
        int c = c2 + cc;
        key2[cc] = ((c >> 3) ^ c) & 7;
    }

    float sum[4][2]   = {{0.f,0.f},{0.f,0.f},{0.f,0.f},{0.f,0.f}};
    float sumsq[4][2] = {{0.f,0.f},{0.f,0.f},{0.f,0.f},{0.f,0.f}};

    __syncthreads();

    for (int i = 0; i < E_; ++i) {
        // ---- input tile: concat(states[i], actions[i]) ----
        for (int idx = tid; idx < TB_ * DS_; idx += NTH_) {
            int b = idx >> 5, d = idx & 31;
            s_inp[b * ISTR_ + d] = states[((size_t)i * B_ + btile + b) * DS_ + d];
        }
        for (int idx = tid; idx < TB_ * DA_; idx += NTH_) {
            int b = idx >> 3, d = idx & 7;
            s_inp[b * ISTR_ + DS_ + d] = actions[((size_t)i * B_ + btile + b) * DA_ + d];
        }
        __syncthreads();

        // ================= layer 0: h0 = leaky(inp @ W0 + b0), K=40 =================
        {
            unsigned long long acc[4][8];
            #pragma unroll
            for (int r = 0; r < 4; ++r)
                #pragma unroll
                for (int cc = 0; cc < 8; ++cc) acc[r][cc] = 0ULL;

            #pragma unroll 2
            for (int g = 0; g < DIN_ / 4; ++g) {           // 10 granules of 4 k
                ulonglong2 a[4];
                #pragma unroll
                for (int r = 0; r < 4; ++r)
                    a[r] = *reinterpret_cast<const ulonglong2*>(
                               s_inp + (r0 + r) * ISTR_ + (g << 2));
                #pragma unroll
                for (int cc = 0; cc < 8; ++cc) {
                    ulonglong2 bv = *reinterpret_cast<const ulonglong2*>(
                        s_w0t + (c0 + cc) * W0K_ + ((g ^ key1[cc]) << 2));
                    #pragma unroll
                    for (int r = 0; r < 4; ++r) {
                        acc[r][cc] = ffma2(a[r].x, bv.x, acc[r][cc]);
                        acc[r][cc] = ffma2(a[r].y, bv.y, acc[r][cc]);
                    }
                }
            }
            #pragma unroll
            for (int r = 0; r < 4; ++r) {
                float v[8];
                #pragma unroll
                for (int cc = 0; cc < 8; ++cc) {
                    float t = hsum2(acc[r][cc]) + s_b0[c0 + cc];
                    v[cc] = t > 0.f ? t : 0.01f * t;
                }
                *(float4*)&s_h0[(r0 + r) * HSTR_ + c0]     = make_float4(v[0], v[1], v[2], v[3]);
                *(float4*)&s_h0[(r0 + r) * HSTR_ + c0 + 4] = make_float4(v[4], v[5], v[6], v[7]);
            }
        }
        __syncthreads();

        // ================= layer 1: h1 = leaky(h0 @ W1 + b1), K=128 =================
        {
            unsigned long long acc[4][8];
            #pragma unroll
            for (int r = 0; r < 4; ++r)
                #pragma unroll
                for (int cc = 0; cc < 8; ++cc) acc[r][cc] = 0ULL;

            #pragma unroll 4
            for (int g = 0; g < HID_ / 4; ++g) {           // 32 granules of 4 k
                ulonglong2 a[4];
                #pragma unroll
                for (int r = 0; r < 4; ++r)
                    a[r] = *reinterpret_cast<const ulonglong2*>(
                               s_h0 + (r0 + r) * HSTR_ + (g << 2));
                #pragma unroll
                for (int cc = 0; cc < 8; ++cc) {
                    ulonglong2 bv = *reinterpret_cast<const ulonglong2*>(
                        s_w1t + (c0 + cc) * W1K_ + ((g ^ key1[cc]) << 2));
                    #pragma unroll
                    for (int r = 0; r < 4; ++r) {
                        acc[r][cc] = ffma2(a[r].x, bv.x, acc[r][cc]);
                        acc[r][cc] = ffma2(a[r].y, bv.y, acc[r][cc]);
                    }
                }
            }
            #pragma unroll
            for (int r = 0; r < 4; ++r) {
                float v[8];
                #pragma unroll
                for (int cc = 0; cc < 8; ++cc) {
                    float t = hsum2(acc[r][cc]) + s_b1[c0 + cc];
                    v[cc] = t > 0.f ? t : 0.01f * t;
                }
                *(float4*)&s_h1[(r0 + r) * HSTR_ + c0]     = make_float4(v[0], v[1], v[2], v[3]);
                *(float4*)&s_h1[(r0 + r) * HSTR_ + c0 + 4] = make_float4(v[4], v[5], v[6], v[7]);
            }
        }
        __syncthreads();

        // ================= layer 2: pred = h1 @ W2 + b2, K=128; stats ===============
        {
            unsigned long long acc[4][2];
            #pragma unroll
            for (int r = 0; r < 4; ++r) { acc[r][0] = 0ULL; acc[r][1] = 0ULL; }

            #pragma unroll 4
            for (int g = 0; g < HID_ / 4; ++g) {
                ulonglong2 a[4];
                #pragma unroll
                for (int r = 0; r < 4; ++r)
                    a[r] = *reinterpret_cast<const ulonglong2*>(
                               s_h1 + (r0 + r) * HSTR_ + (g << 2));
                #pragma unroll
                for (int cc = 0; cc < 2; ++cc) {
                    ulonglong2 bv = *reinterpret_cast<const ulonglong2*>(
                        s_w2t + (c2 + cc) * W2K_ + ((g ^ key2[cc]) << 2));
                    #pragma unroll
                    for (int r = 0; r < 4; ++r) {
                        acc[r][cc] = ffma2(a[r].x, bv.x, acc[r][cc]);
                        acc[r][cc] = ffma2(a[r].y, bv.y, acc[r][cc]);
                    }
                }
            }
            #pragma unroll
            for (int r = 0; r < 4; ++r)
                #pragma unroll
                for (int cc = 0; cc < 2; ++cc) {
                    float p = hsum2(acc[r][cc]) + s_b2[c2 + cc];
                    sum[r][cc]   += p;
                    sumsq[r][cc]  = fmaf(p, p, sumsq[r][cc]);
                }
        }
        __syncthreads();  // protect buffers before next i
    }

    // ---- epilogue: mean/var over i, add states[j] ----
    const size_t var_off = (size_t)E_ * B_ * DS_;
    #pragma unroll
    for (int r = 0; r < 4; ++r) {
        const size_t b = (size_t)btile + r0 + r;
        #pragma unroll
        for (int cc = 0; cc < 2; ++cc) {
            const int k = c2 + cc;
            const size_t o = ((size_t)j * B_ + b) * DS_ + k;
            float mean = sum[r][cc] * (1.0f / E_);
            float var  = (sumsq[r][cc] - (float)E_ * mean * mean) * (1.0f / (E_ - 1));
            out[o]           = mean + states[o];
            out[var_off + o] = var;
        }
    }
}

extern "C" void kernel_launch(void* const* d_in, const int* in_sizes, int n_in,
                              void* d_out, int out_size)
{
    const float* states  = (const float*)d_in[0];
    const float* actions = (const float*)d_in[1];
    const float* W0      = (const float*)d_in[2];
    const float* b0      = (const float*)d_in[3];
    const float* W1      = (const float*)d_in[4];
    const float* b1      = (const float*)d_in[5];
    const float* W2      = (const float*)d_in[6];
    const float* b2      = (const float*)d_in[7];
    float* out = (float*)d_out;

    const int smem_bytes = SMEM_FLOATS_ * (int)sizeof(float);
    cudaFuncSetAttribute(ensemble_mlp_kernel,
                         cudaFuncAttributeMaxDynamicSharedMemorySize, smem_bytes);

    dim3 grid(B_ / TB_, E_);   // 256 x 8 = 2048 CTAs
    dim3 block(NTH_);
    ensemble_mlp_kernel<<<grid, block, smem_bytes>>>(states, actions,
                                                     W0, b0, W1, b1, W2, b2, out);
}

// round 4
// speedup vs baseline: 3.8789x; 3.2489x over previous
#include <cuda_runtime.h>
#include <cstdint>

// ===== problem constants =====
#define E_   8
#define B_   16384
#define DS_  32
#define DA_  8
#define DIN_ 40
#define HID_ 128
#define TM_  128     // batch rows per CTA
#define NTH_ 256     // 8 warps

// ===== SMEM layout (bytes) =====
// X tile: 128 rows x 56 f32 (cols 0..39 data, 40..47 zero pad, 48..55 dead pad)
#define XSTR_  56
#define SM_X   0
#define SM_W0  28672                       // 128 n x S0, S0=192  -> 24576
#define S0_    192
#define SM_W1  (SM_W0 + 24576)             // 128 n x S1, S1=576  -> 73728
#define S1_    576
#define SM_W2  (SM_W1 + 73728)             // 32 n x S2, S2=576   -> 18432
#define S2_    576
#define SM_BI  (SM_W2 + 18432)             // b0(512) b1(512) b2(128)
#define SM_TOTAL (SM_BI + 1152)            // 146560 bytes

// ===== helpers =====
__device__ __forceinline__ uint32_t pack2(float lo, float hi) {
    uint32_t d;
    asm("cvt.rn.bf16x2.f32 %0, %1, %2;" : "=r"(d) : "f"(hi), "f"(lo));
    return d;
}
__device__ __forceinline__ float blo(uint32_t u) { return __uint_as_float(u << 16); }
__device__ __forceinline__ float bhi(uint32_t u) { return __uint_as_float(u & 0xFFFF0000u); }

__device__ __forceinline__ void mma16816(float d[4], const uint32_t a[4],
                                         uint32_t b0, uint32_t b1) {
    asm volatile(
        "mma.sync.aligned.m16n8k16.row.col.f32.bf16.bf16.f32 "
        "{%0,%1,%2,%3}, {%4,%5,%6,%7}, {%8,%9}, {%0,%1,%2,%3};"
        : "+f"(d[0]), "+f"(d[1]), "+f"(d[2]), "+f"(d[3])
        : "r"(a[0]), "r"(a[1]), "r"(a[2]), "r"(a[3]), "r"(b0), "r"(b1));
}

// bias + leaky + bf16 hi/lo split of one accumulator ntile
__device__ __forceinline__ void cvt_split(const float acc[4], float2 bb,
                                          uint32_t& h01, uint32_t& h23,
                                          uint32_t& l01, uint32_t& l23) {
    float v0 = acc[0] + bb.x, v1 = acc[1] + bb.y;
    float v2 = acc[2] + bb.x, v3 = acc[3] + bb.y;
    v0 = fmaxf(v0, 0.01f * v0); v1 = fmaxf(v1, 0.01f * v1);
    v2 = fmaxf(v2, 0.01f * v2); v3 = fmaxf(v3, 0.01f * v3);
    h01 = pack2(v0, v1);
    h23 = pack2(v2, v3);
    l01 = pack2(v0 - blo(h01), v1 - bhi(h01));
    l23 = pack2(v2 - blo(h23), v3 - bhi(h23));
}

// split a float2 (two consecutive-k activations) into hi/lo bf16x2
__device__ __forceinline__ void split_x(float2 x, uint32_t& h, uint32_t& l) {
    h = pack2(x.x, x.y);
    l = pack2(x.x - blo(h), x.y - bhi(h));
}

// stage one weight matrix [Kreal][N] (row-major) into fragment-native hi/lo SMEM
__device__ void stage_w(const float* __restrict__ g, int Kreal, int Kc, int N,
                        char* dst, int S) {
    const int total = N * Kc * 4;
    for (int idx = threadIdx.x; idx < total; idx += NTH_) {
        int n = idx % N;
        int rest = idx / N;
        int q = rest & 3;
        int kc = rest >> 2;
        int k0 = kc * 16 + q * 2;
        float f0 = (k0     < Kreal) ? g[(size_t)k0 * N + n]       : 0.f;
        float f1 = (k0 + 1 < Kreal) ? g[(size_t)(k0 + 1) * N + n] : 0.f;
        float f2 = (k0 + 8 < Kreal) ? g[(size_t)(k0 + 8) * N + n] : 0.f;
        float f3 = (k0 + 9 < Kreal) ? g[(size_t)(k0 + 9) * N + n] : 0.f;
        uint32_t h01 = pack2(f0, f1);
        uint32_t h23 = pack2(f2, f3);
        uint32_t l01 = pack2(f0 - blo(h01), f1 - bhi(h01));
        uint32_t l23 = pack2(f2 - blo(h23), f3 - bhi(h23));
        *(uint4*)(dst + (size_t)n * S + kc * 64 + q * 16) =
            make_uint4(h01, h23, l01, l23);
    }
}

__global__ __launch_bounds__(NTH_, 1)
void ensemble_mlp_mma(const float* __restrict__ states,
                      const float* __restrict__ actions,
                      const float* __restrict__ W0, const float* __restrict__ b0,
                      const float* __restrict__ W1, const float* __restrict__ b1,
                      const float* __restrict__ W2, const float* __restrict__ b2,
                      float* __restrict__ out)
{
    extern __shared__ char smc[];
    float* sX  = (float*)(smc + SM_X);
    char*  w0p = smc + SM_W0;
    char*  w1p = smc + SM_W1;
    char*  w2p = smc + SM_W2;
    float* sb0 = (float*)(smc + SM_BI);
    float* sb1 = sb0 + 128;
    float* sb2 = sb1 + 128;

    const int tid  = threadIdx.x;
    const int wid  = tid >> 5;
    const int lane = tid & 31;
    const int qk   = lane & 3;     // k-quad within fragment
    const int rr   = lane >> 2;    // row (and B-col) within fragment
    const int j     = blockIdx.y;
    const int btile = blockIdx.x * TM_;

    // ---- stage weights (hi/lo bf16, fragment-native) + biases ----
    stage_w(W0 + (size_t)j * DIN_ * HID_, DIN_, 3, HID_, w0p, S0_);
    stage_w(W1 + (size_t)j * HID_ * HID_, HID_, 8, HID_, w1p, S1_);
    stage_w(W2 + (size_t)j * HID_ * DS_,  HID_, 8, DS_,  w2p, S2_);
    if (tid < HID_) { sb0[tid] = b0[j * HID_ + tid]; sb1[tid] = b1[j * HID_ + tid]; }
    if (tid < DS_)  { sb2[tid] = b2[j * DS_ + tid]; }
    // zero X pad cols 40..47 (never rewritten inside the i loop)
    for (int idx = tid; idx < TM_ * 8; idx += NTH_) {
        int b = idx >> 3, d = idx & 7;
        sX[b * XSTR_ + 40 + d] = 0.f;
    }

    float sums[16], sqs[16];
    #pragma unroll
    for (int t = 0; t < 16; ++t) { sums[t] = 0.f; sqs[t] = 0.f; }

    uint32_t aH[32], aL[32];
    const int rbase = wid * 16 + rr;   // this thread's low row within CTA tile

    for (int i = 0; i < E_; ++i) {
        __syncthreads();   // previous iteration's reads of sX complete
        // ---- stage X tile (coalesced) ----
        for (int idx = tid; idx < TM_ * DS_; idx += NTH_) {
            int b = idx >> 5, d = idx & 31;
            sX[b * XSTR_ + d] = states[((size_t)i * B_ + btile + b) * DS_ + d];
        }
        for (int idx = tid; idx < TM_ * DA_; idx += NTH_) {
            int b = idx >> 3, d = idx & 7;
            sX[b * XSTR_ + DS_ + d] = actions[((size_t)i * B_ + btile + b) * DA_ + d];
        }
        __syncthreads();

        // ================= layer 0: K=48 (padded), N=128 =================
        {
            float acc[16][4];
            #pragma unroll
            for (int nt = 0; nt < 16; ++nt)
                #pragma unroll
                for (int t = 0; t < 4; ++t) acc[nt][t] = 0.f;

            #pragma unroll
            for (int kc = 0; kc < 3; ++kc) {
                const float* xb = sX + (size_t)rbase * XSTR_ + kc * 16 + qk * 2;
                float2 x00 = *(const float2*)(xb);                // row lo, k lo
                float2 x01 = *(const float2*)(xb + 8 * XSTR_);    // row hi, k lo
                float2 x10 = *(const float2*)(xb + 8);            // row lo, k hi
                float2 x11 = *(const float2*)(xb + 8 * XSTR_ + 8);// row hi, k hi
                uint32_t ah[4], al[4];
                split_x(x00, ah[0], al[0]);
                split_x(x01, ah[1], al[1]);
                split_x(x10, ah[2], al[2]);
                split_x(x11, ah[3], al[3]);
                #pragma unroll
                for (int nt = 0; nt < 16; ++nt) {
                    uint4 bv = *(const uint4*)(w0p + (size_t)(nt * 8 + rr) * S0_
                                               + kc * 64 + qk * 16);
                    mma16816(acc[nt], ah, bv.x, bv.y);  // Ahi*Bhi
                    mma16816(acc[nt], ah, bv.z, bv.w);  // Ahi*Blo
                    mma16816(acc[nt], al, bv.x, bv.y);  // Alo*Bhi
                }
            }
            #pragma unroll
            for (int nt = 0; nt < 16; ++nt) {
                float2 bb = *(const float2*)(sb0 + nt * 8 + qk * 2);
                cvt_split(acc[nt], bb, aH[2*nt], aH[2*nt+1], aL[2*nt], aL[2*nt+1]);
            }
        }

        // ================= layer 1: K=128, N=128 =================
        {
            float acc[16][4];
            #pragma unroll
            for (int nt = 0; nt < 16; ++nt)
                #pragma unroll
                for (int t = 0; t < 4; ++t) acc[nt][t] = 0.f;

            #pragma unroll
            for (int kc = 0; kc < 8; ++kc) {
                const uint32_t* ah = aH + 4 * kc;
                const uint32_t* al = aL + 4 * kc;
                #pragma unroll
                for (int nt = 0; nt < 16; ++nt) {
                    uint4 bv = *(const uint4*)(w1p + (size_t)(nt * 8 + rr) * S1_
                                               + kc * 64 + qk * 16);
                    mma16816(acc[nt], ah, bv.x, bv.y);
                    mma16816(acc[nt], ah, bv.z, bv.w);
                    mma16816(acc[nt], al, bv.x, bv.y);
                }
            }
            #pragma unroll
            for (int nt = 0; nt < 16; ++nt) {
                float2 bb = *(const float2*)(sb1 + nt * 8 + qk * 2);
                cvt_split(acc[nt], bb, aH[2*nt], aH[2*nt+1], aL[2*nt], aL[2*nt+1]);
            }
        }

        // ================= layer 2: K=128, N=32; accumulate stats =================
        {
            float acc[4][4];
            #pragma unroll
            for (int nt = 0; nt < 4; ++nt)
                #pragma unroll
                for (int t = 0; t < 4; ++t) acc[nt][t] = 0.f;

            #pragma unroll
            for (int kc = 0; kc < 8; ++kc) {
                const uint32_t* ah = aH + 4 * kc;
                const uint32_t* al = aL + 4 * kc;
                #pragma unroll
                for (int nt = 0; nt < 4; ++nt) {
                    uint4 bv = *(const uint4*)(w2p + (size_t)(nt * 8 + rr) * S2_
                                               + kc * 64 + qk * 16);
                    mma16816(acc[nt], ah, bv.x, bv.y);
                    mma16816(acc[nt], ah, bv.z, bv.w);
                    mma16816(acc[nt], al, bv.x, bv.y);
                }
            }
            #pragma unroll
            for (int nt = 0; nt < 4; ++nt) {
                float2 bb = *(const float2*)(sb2 + nt * 8 + qk * 2);
                float p0 = acc[nt][0] + bb.x;
                float p1 = acc[nt][1] + bb.y;
                float p2 = acc[nt][2] + bb.x;
                float p3 = acc[nt][3] + bb.y;
                sums[nt*4+0] += p0; sqs[nt*4+0] = fmaf(p0, p0, sqs[nt*4+0]);
                sums[nt*4+1] += p1; sqs[nt*4+1] = fmaf(p1, p1, sqs[nt*4+1]);
                sums[nt*4+2] += p2; sqs[nt*4+2] = fmaf(p2, p2, sqs[nt*4+2]);
                sums[nt*4+3] += p3; sqs[nt*4+3] = fmaf(p3, p3, sqs[nt*4+3]);
            }
        }
    }

    // ---- epilogue: mean/var over the 8 members; outputs ----
    const size_t var_off = (size_t)E_ * B_ * DS_;
    const size_t row_lo = (size_t)j * B_ + btile + rbase;
    const size_t row_hi = row_lo + 8;
    #pragma unroll
    for (int nt = 0; nt < 4; ++nt) {
        const int c0 = nt * 8 + qk * 2;
        // row lo (acc elements 0,1)
        {
            const size_t o = row_lo * DS_ + c0;
            float2 st = *(const float2*)(states + o);
            float m0 = sums[nt*4+0] * 0.125f;
            float m1 = sums[nt*4+1] * 0.125f;
            float v0 = (sqs[nt*4+0] - 8.f * m0 * m0) * (1.f / 7.f);
            float v1 = (sqs[nt*4+1] - 8.f * m1 * m1) * (1.f / 7.f);
            *(float2*)(out + o)           = make_float2(m0 + st.x, m1 + st.y);
            *(float2*)(out + var_off + o) = make_float2(v0, v1);
        }
        // row hi (acc elements 2,3)
        {
            const size_t o = row_hi * DS_ + c0;
            float2 st = *(const float2*)(states + o);
            float m2 = sums[nt*4+2] * 0.125f;
            float m3 = sums[nt*4+3] * 0.125f;
            float v2 = (sqs[nt*4+2] - 8.f * m2 * m2) * (1.f / 7.f);
            float v3 = (sqs[nt*4+3] - 8.f * m3 * m3) * (1.f / 7.f);
            *(float2*)(out + o)           = make_float2(m2 + st.x, m3 + st.y);
            *(float2*)(out + var_off + o) = make_float2(v2, v3);
        }
    }
}

extern "C" void kernel_launch(void* const* d_in, const int* in_sizes, int n_in,
                              void* d_out, int out_size)
{
    const float* states  = (const float*)d_in[0];
    const float* actions = (const float*)d_in[1];
    const float* W0      = (const float*)d_in[2];
    const float* b0      = (const float*)d_in[3];
    const float* W1      = (const float*)d_in[4];
    const float* b1      = (const float*)d_in[5];
    const float* W2      = (const float*)d_in[6];
    const float* b2      = (const float*)d_in[7];
    float* out = (float*)d_out;

    cudaFuncSetAttribute(ensemble_mlp_mma,
                         cudaFuncAttributeMaxDynamicSharedMemorySize, SM_TOTAL);

    dim3 grid(B_ / TM_, E_);   // 128 x 8 = 1024 CTAs
    ensemble_mlp_mma<<<grid, NTH_, SM_TOTAL>>>(states, actions,
                                               W0, b0, W1, b1, W2, b2, out);
}

// round 5
// speedup vs baseline: 4.6695x; 1.2038x over previous
#include <cuda_runtime.h>
#include <cstdint>

// ===== problem constants =====
#define E_   8
#define B_   16384
#define DS_  32
#define DA_  8
#define DIN_ 40
#define HID_ 128
#define TM_  128     // batch rows per CTA
#define NTH_ 256     // 8 warps x 16 rows

// ===== SMEM: fragment-linear weights; block (kc,nt) = 512 B, lane = 16 B =====
#define SM_W0  0                         // 3 kc * 16 nt * 512  = 24576
#define SM_W1  24576                     // 8 kc * 16 nt * 512  = 65536
#define SM_W2  90112                     // 8 kc *  4 nt * 512  = 16384
#define SM_BI  106496                    // b0(512) b1(512) b2(128)
#define SM_TOTAL (SM_BI + 1152)          // 107648 bytes

// ===== helpers =====
__device__ __forceinline__ uint32_t pack2(float lo, float hi) {
    uint32_t d;
    asm("cvt.rn.bf16x2.f32 %0, %1, %2;" : "=r"(d) : "f"(hi), "f"(lo));
    return d;
}
__device__ __forceinline__ float blo(uint32_t u) { return __uint_as_float(u << 16); }
__device__ __forceinline__ float bhi(uint32_t u) { return __uint_as_float(u & 0xFFFF0000u); }

__device__ __forceinline__ void mma16816(float d[4], const uint32_t a[4],
                                         uint32_t b0, uint32_t b1) {
    asm volatile(
        "mma.sync.aligned.m16n8k16.row.col.f32.bf16.bf16.f32 "
        "{%0,%1,%2,%3}, {%4,%5,%6,%7}, {%8,%9}, {%0,%1,%2,%3};"
        : "+f"(d[0]), "+f"(d[1]), "+f"(d[2]), "+f"(d[3])
        : "r"(a[0]), "r"(a[1]), "r"(a[2]), "r"(a[3]), "r"(b0), "r"(b1));
}

// bias + leaky + bf16 hi/lo split of one accumulator ntile
__device__ __forceinline__ void cvt_split(const float acc[4], float2 bb,
                                          uint32_t& h01, uint32_t& h23,
                                          uint32_t& l01, uint32_t& l23) {
    float v0 = acc[0] + bb.x, v1 = acc[1] + bb.y;
    float v2 = acc[2] + bb.x, v3 = acc[3] + bb.y;
    v0 = fmaxf(v0, 0.01f * v0); v1 = fmaxf(v1, 0.01f * v1);
    v2 = fmaxf(v2, 0.01f * v2); v3 = fmaxf(v3, 0.01f * v3);
    h01 = pack2(v0, v1);
    h23 = pack2(v2, v3);
    l01 = pack2(v0 - blo(h01), v1 - bhi(h01));
    l23 = pack2(v2 - blo(h23), v3 - bhi(h23));
}

__device__ __forceinline__ void split_x(float2 x, uint32_t& h, uint32_t& l) {
    h = pack2(x.x, x.y);
    l = pack2(x.x - blo(h), x.y - bhi(h));
}

// stage one weight matrix [Kreal][N] row-major into fragment-linear hi/lo SMEM
__device__ void stage_w(const float* __restrict__ g, int Kreal, int KC, int NT,
                        int N, char* dst) {
    const int total = KC * NT * 32;
    for (int idx = threadIdx.x; idx < total; idx += NTH_) {
        int lane = idx & 31;
        int blk  = idx >> 5;
        int qk = lane & 3, rr = lane >> 2;
        int nt = blk % NT, kc = blk / NT;
        int n  = nt * 8 + rr;
        int k0 = kc * 16 + qk * 2;
        float f0 = (k0     < Kreal) ? g[(size_t)k0 * N + n]       : 0.f;
        float f1 = (k0 + 1 < Kreal) ? g[(size_t)(k0 + 1) * N + n] : 0.f;
        float f2 = (k0 + 8 < Kreal) ? g[(size_t)(k0 + 8) * N + n] : 0.f;
        float f3 = (k0 + 9 < Kreal) ? g[(size_t)(k0 + 9) * N + n] : 0.f;
        uint32_t h01 = pack2(f0, f1);
        uint32_t h23 = pack2(f2, f3);
        uint32_t l01 = pack2(f0 - blo(h01), f1 - bhi(h01));
        uint32_t l23 = pack2(f2 - blo(h23), f3 - bhi(h23));
        *(uint4*)(dst + (size_t)blk * 512 + lane * 16) = make_uint4(h01, h23, l01, l23);
    }
}

__global__ __launch_bounds__(NTH_, 1)
void ensemble_mlp_mma(const float* __restrict__ states,
                      const float* __restrict__ actions,
                      const float* __restrict__ W0, const float* __restrict__ b0,
                      const float* __restrict__ W1, const float* __restrict__ b1,
                      const float* __restrict__ W2, const float* __restrict__ b2,
                      float* __restrict__ out)
{
    extern __shared__ char smc[];
    float* sb0 = (float*)(smc + SM_BI);
    float* sb1 = sb0 + 128;
    float* sb2 = sb1 + 128;

    const int tid  = threadIdx.x;
    const int wid  = tid >> 5;
    const int lane = tid & 31;
    const int qk   = lane & 3;     // k-quad within fragment
    const int rr   = lane >> 2;    // row (and B-col) within fragment
    const int j     = blockIdx.y;
    const int btile = blockIdx.x * TM_;
    const int rbase = wid * 16 + rr;

    // ---- stage weights (fragment-linear hi/lo bf16) + biases ----
    stage_w(W0 + (size_t)j * DIN_ * HID_, DIN_, 3, 16, HID_, smc + SM_W0);
    stage_w(W1 + (size_t)j * HID_ * HID_, HID_, 8, 16, HID_, smc + SM_W1);
    stage_w(W2 + (size_t)j * HID_ * DS_,  HID_, 8,  4, DS_,  smc + SM_W2);
    if (tid < HID_) { sb0[tid] = b0[j * HID_ + tid]; sb1[tid] = b1[j * HID_ + tid]; }
    if (tid < DS_)  { sb2[tid] = b2[j * DS_ + tid]; }
    __syncthreads();   // the ONLY barrier — i-loop below is barrier-free

    // per-lane fragment base pointers (inner offsets are compile-time constants)
    const char* w0b = smc + SM_W0 + lane * 16;
    const char* w1b = smc + SM_W1 + lane * 16;
    const char* w2b = smc + SM_W2 + lane * 16;

    // per-thread gmem activation pointers (advance by one i-slice per iter)
    const float* srow = states  + ((size_t)btile + rbase) * DS_ + qk * 2;
    const float* arow = actions + ((size_t)btile + rbase) * DA_ + qk * 2;

    float sums[16], sqs[16];
    #pragma unroll
    for (int t = 0; t < 16; ++t) { sums[t] = 0.f; sqs[t] = 0.f; }

    uint32_t aH[32], aL[32];

    for (int i = 0; i < E_; ++i) {
        // ================= layer 0: K=48 (40 real), N=128 =================
        {
            float acc[16][4];
            #pragma unroll
            for (int nt = 0; nt < 16; ++nt)
                #pragma unroll
                for (int t = 0; t < 4; ++t) acc[nt][t] = 0.f;

            // kc = 0,1 : all from states
            #pragma unroll
            for (int kc = 0; kc < 2; ++kc) {
                float2 x00 = __ldg((const float2*)(srow + kc * 16));
                float2 x01 = __ldg((const float2*)(srow + kc * 16 + 8 * DS_));
                float2 x10 = __ldg((const float2*)(srow + kc * 16 + 8));
                float2 x11 = __ldg((const float2*)(srow + kc * 16 + 8 + 8 * DS_));
                uint32_t ah[4], al[4];
                split_x(x00, ah[0], al[0]);
                split_x(x01, ah[1], al[1]);
                split_x(x10, ah[2], al[2]);
                split_x(x11, ah[3], al[3]);
                #pragma unroll
                for (int nt = 0; nt < 16; ++nt) {
                    uint4 bv = *(const uint4*)(w0b + (kc * 16 + nt) * 512);
                    mma16816(acc[nt], ah, bv.x, bv.y);
                    mma16816(acc[nt], ah, bv.z, bv.w);
                    mma16816(acc[nt], al, bv.x, bv.y);
                }
            }
            // kc = 2 : k 32..39 from actions, k 40..47 zero
            {
                float2 x00 = __ldg((const float2*)(arow));
                float2 x01 = __ldg((const float2*)(arow + 8 * DA_));
                uint32_t ah[4], al[4];
                split_x(x00, ah[0], al[0]);
                split_x(x01, ah[1], al[1]);
                ah[2] = al[2] = 0u;
                ah[3] = al[3] = 0u;
                #pragma unroll
                for (int nt = 0; nt < 16; ++nt) {
                    uint4 bv = *(const uint4*)(w0b + (2 * 16 + nt) * 512);
                    mma16816(acc[nt], ah, bv.x, bv.y);
                    mma16816(acc[nt], ah, bv.z, bv.w);
                    mma16816(acc[nt], al, bv.x, bv.y);
                }
            }
            #pragma unroll
            for (int nt = 0; nt < 16; ++nt) {
                float2 bb = *(const float2*)(sb0 + nt * 8 + qk * 2);
                cvt_split(acc[nt], bb, aH[2*nt], aH[2*nt+1], aL[2*nt], aL[2*nt+1]);
            }
        }

        // ================= layer 1: K=128, N=128 =================
        {
            float acc[16][4];
            #pragma unroll
            for (int nt = 0; nt < 16; ++nt)
                #pragma unroll
                for (int t = 0; t < 4; ++t) acc[nt][t] = 0.f;

            #pragma unroll
            for (int kc = 0; kc < 8; ++kc) {
                const uint32_t* ah = aH + 4 * kc;
                const uint32_t* al = aL + 4 * kc;
                #pragma unroll
                for (int nt = 0; nt < 16; ++nt) {
                    uint4 bv = *(const uint4*)(w1b + (kc * 16 + nt) * 512);
                    mma16816(acc[nt], ah, bv.x, bv.y);
                    mma16816(acc[nt], ah, bv.z, bv.w);
                    mma16816(acc[nt], al, bv.x, bv.y);
                }
            }
            #pragma unroll
            for (int nt = 0; nt < 16; ++nt) {
                float2 bb = *(const float2*)(sb1 + nt * 8 + qk * 2);
                cvt_split(acc[nt], bb, aH[2*nt], aH[2*nt+1], aL[2*nt], aL[2*nt+1]);
            }
        }

        // ================= layer 2: K=128, N=32; stats =================
        {
            float acc[4][4];
            #pragma unroll
            for (int nt = 0; nt < 4; ++nt)
                #pragma unroll
                for (int t = 0; t < 4; ++t) acc[nt][t] = 0.f;

            #pragma unroll
            for (int kc = 0; kc < 8; ++kc) {
                const uint32_t* ah = aH + 4 * kc;
                const uint32_t* al = aL + 4 * kc;
                #pragma unroll
                for (int nt = 0; nt < 4; ++nt) {
                    uint4 bv = *(const uint4*)(w2b + (kc * 4 + nt) * 512);
                    mma16816(acc[nt], ah, bv.x, bv.y);
                    mma16816(acc[nt], ah, bv.z, bv.w);
                    mma16816(acc[nt], al, bv.x, bv.y);
                }
            }
            #pragma unroll
            for (int nt = 0; nt < 4; ++nt) {
                float2 bb = *(const float2*)(sb2 + nt * 8 + qk * 2);
                float p0 = acc[nt][0] + bb.x;
                float p1 = acc[nt][1] + bb.y;
                float p2 = acc[nt][2] + bb.x;
                float p3 = acc[nt][3] + bb.y;
                sums[nt*4+0] += p0; sqs[nt*4+0] = fmaf(p0, p0, sqs[nt*4+0]);
                sums[nt*4+1] += p1; sqs[nt*4+1] = fmaf(p1, p1, sqs[nt*4+1]);
                sums[nt*4+2] += p2; sqs[nt*4+2] = fmaf(p2, p2, sqs[nt*4+2]);
                sums[nt*4+3] += p3; sqs[nt*4+3] = fmaf(p3, p3, sqs[nt*4+3]);
            }
        }

        srow += (size_t)B_ * DS_;
        arow += (size_t)B_ * DA_;
    }

    // ---- epilogue: mean/var over the 8 members; outputs ----
    const size_t var_off = (size_t)E_ * B_ * DS_;
    const size_t row_lo = (size_t)j * B_ + btile + rbase;
    const size_t row_hi = row_lo + 8;
    #pragma unroll
    for (int nt = 0; nt < 4; ++nt) {
        const int c0 = nt * 8 + qk * 2;
        {
            const size_t o = row_lo * DS_ + c0;
            float2 st = __ldg((const float2*)(states + o));
            float m0 = sums[nt*4+0] * 0.125f;
            float m1 = sums[nt*4+1] * 0.125f;
            float v0 = (sqs[nt*4+0] - 8.f * m0 * m0) * (1.f / 7.f);
            float v1 = (sqs[nt*4+1] - 8.f * m1 * m1) * (1.f / 7.f);
            *(float2*)(out + o)           = make_float2(m0 + st.x, m1 + st.y);
            *(float2*)(out + var_off + o) = make_float2(v0, v1);
        }
        {
            const size_t o = row_hi * DS_ + c0;
            float2 st = __ldg((const float2*)(states + o));
            float m2 = sums[nt*4+2] * 0.125f;
            float m3 = sums[nt*4+3] * 0.125f;
            float v2 = (sqs[nt*4+2] - 8.f * m2 * m2) * (1.f / 7.f);
            float v3 = (sqs[nt*4+3] - 8.f * m3 * m3) * (1.f / 7.f);
            *(float2*)(out + o)           = make_float2(m2 + st.x, m3 + st.y);
            *(float2*)(out + var_off + o) = make_float2(v2, v3);
        }
    }
}

extern "C" void kernel_launch(void* const* d_in, const int* in_sizes, int n_in,
                              void* d_out, int out_size)
{
    const float* states  = (const float*)d_in[0];
    const float* actions = (const float*)d_in[1];
    const float* W0      = (const float*)d_in[2];
    const float* b0      = (const float*)d_in[3];
    const float* W1      = (const float*)d_in[4];
    const float* b1      = (const float*)d_in[5];
    const float* W2      = (const float*)d_in[6];
    const float* b2      = (const float*)d_in[7];
    float* out = (float*)d_out;

    cudaFuncSetAttribute(ensemble_mlp_mma,
                         cudaFuncAttributeMaxDynamicSharedMemorySize, SM_TOTAL);

    dim3 grid(B_ / TM_, E_);   // 128 x 8 = 1024 CTAs
    ensemble_mlp_mma<<<grid, NTH_, SM_TOTAL>>>(states, actions,
                                               W0, b0, W1, b1, W2, b2, out);
}